// round 5
// baseline (speedup 1.0000x reference)
#include <cuda_runtime.h>

#define C_DIM 512
#define K_DIM 19
#define HW    16384
#define B_DIM 8
#define S_CHUNKS 16
#define NHALF (B_DIM * K_DIM * HW)     // elements per csplit partial half

typedef unsigned long long u64;

// ---- f32x2 packed helpers ----
__device__ __forceinline__ u64 pk2(float lo, float hi) {
    u64 r; asm("mov.b64 %0, {%1, %2};" : "=l"(r) : "f"(lo), "f"(hi)); return r;
}
__device__ __forceinline__ void upk2(u64 v, float& lo, float& hi) {
    asm("mov.b64 {%0, %1}, %2;" : "=f"(lo), "=f"(hi) : "l"(v));
}
__device__ __forceinline__ u64 ffma2(u64 a, u64 b, u64 c) {
    u64 d; asm("fma.rn.f32x2 %0, %1, %2, %3;" : "=l"(d) : "l"(a), "l"(b), "l"(c)); return d;
}

// Static scratch
__device__ float g_pre[2 * NHALF];                            // csplit partials (19.9MB)
__device__ float g_partial[B_DIM * S_CHUNKS * K_DIM * C_DIM]; // pooling partials
__device__ float g_filters[B_DIM * K_DIM * C_DIM];            // dynamic filters

// ============================================================
// K1: pre-mask partial over half the channels.
// grid (32 pos-tiles, 2 csplit, 8 b), 256 thr, 2 pos/thread.
// Weights pre-duplicated in smem; LDS.128 = dup'd pairs for 2 channels.
// ============================================================
__global__ void __launch_bounds__(256) k_mask(
    const float* __restrict__ x, const float* __restrict__ Wm,
    const float* __restrict__ bm)
{
    __shared__ __align__(16) u64 wd[K_DIM * 256];   // 38912 B
    int tid = threadIdx.x;
    int split = blockIdx.y, b = blockIdx.z;
    int c0 = split * 256;

    for (int i = tid; i < K_DIM * 256; i += 256) {
        float w = Wm[(i >> 8) * C_DIM + c0 + (i & 255)];
        wd[i] = pk2(w, w);
    }
    __syncthreads();

    int p0 = blockIdx.x * 512 + tid * 2;
    const float* xb = x + ((size_t)b * C_DIM + c0) * HW + p0;

    u64 a[K_DIM];
    #pragma unroll
    for (int k = 0; k < K_DIM; k++) {
        float bv = (split == 0) ? __ldg(&bm[k]) : 0.0f;
        a[k] = pk2(bv, bv);
    }

    #pragma unroll 2
    for (int c = 0; c < 256; c += 2) {
        u64 x0 = *(const u64*)(xb + (size_t)(c + 0) * HW);
        u64 x1 = *(const u64*)(xb + (size_t)(c + 1) * HW);
        #pragma unroll
        for (int k = 0; k < K_DIM; k++) {
            ulonglong2 w = *(const ulonglong2*)&wd[k * 256 + c];  // broadcast LDS.128
            a[k] = ffma2(w.x, x0, a[k]);
            a[k] = ffma2(w.y, x1, a[k]);
        }
    }

    float* gp = g_pre + (size_t)split * NHALF + ((size_t)b * K_DIM) * HW + p0;
    #pragma unroll
    for (int k = 0; k < K_DIM; k++)
        *(u64*)(gp + (size_t)k * HW) = a[k];
}

// ============================================================
// K1b: mask = sigmoid(half0 + half1) -> d_out. float4 vectorized.
// grid 2432 x 256 (NHALF/4/256 = 2432 exactly).
// ============================================================
__global__ void __launch_bounds__(256) k_sig(float* __restrict__ out)
{
    int i = blockIdx.x * 256 + threadIdx.x;
    float4 u = ((const float4*)g_pre)[i];
    float4 v = ((const float4*)(g_pre + NHALF))[i];
    float4 r;
    r.x = 1.0f / (1.0f + __expf(-(u.x + v.x)));
    r.y = 1.0f / (1.0f + __expf(-(u.y + v.y)));
    r.z = 1.0f / (1.0f + __expf(-(u.z + v.z)));
    r.w = 1.0f / (1.0f + __expf(-(u.w + v.w)));
    ((float4*)out)[i] = r;
}

// ============================================================
// K2: pooling partials. grid (16 chunks, 2 csplit, 8 b), 256 thr (8 warps).
// Chunk = 1024 positions staged as pairs in smem; warp handles 16 ch-pairs
// of its csplit half; one mask LDS.64 feeds 2 FFMA2s; shfl reduce.
// ============================================================
__global__ void __launch_bounds__(256, 2) k_pool(
    const float* __restrict__ x, const float* __restrict__ mask)
{
    extern __shared__ u64 m2[];   // [K_DIM][512] pairs = 77824 B
    int tid = threadIdx.x;
    int chunk = blockIdx.x, split = blockIdx.y, b = blockIdx.z;
    int p0 = chunk * 1024;

    for (int i = tid; i < K_DIM * 512; i += 256) {
        int k = i >> 9, j = i & 511;
        m2[i] = *(const u64*)(mask + ((size_t)b * K_DIM + k) * HW + p0 + 2 * j);
    }
    __syncthreads();

    int warp = tid >> 5, lane = tid & 31;
    const float inv = 1.0f / (float)HW;
    const float* xbase = x + (size_t)b * C_DIM * HW + p0;
    int cpbase = split * 128;

    for (int i = 0; i < 16; i++) {
        int cp = cpbase + warp + 8 * i;
        int c0 = 2 * cp, c1 = c0 + 1;
        const float* x0p = xbase + (size_t)c0 * HW;
        const float* x1p = xbase + (size_t)c1 * HW;

        u64 a0[K_DIM], a1[K_DIM];
        #pragma unroll
        for (int k = 0; k < K_DIM; k++) { a0[k] = 0ull; a1[k] = 0ull; }

        #pragma unroll 2
        for (int t = 0; t < 16; t++) {
            int idx = lane + 32 * t;
            u64 xv0 = *(const u64*)(x0p + 2 * idx);
            u64 xv1 = *(const u64*)(x1p + 2 * idx);
            #pragma unroll
            for (int k = 0; k < K_DIM; k++) {
                u64 m = m2[k * 512 + idx];
                a0[k] = ffma2(m, xv0, a0[k]);
                a1[k] = ffma2(m, xv1, a1[k]);
            }
        }

        #pragma unroll
        for (int k = 0; k < K_DIM; k++) {
            float lo, hi;
            upk2(a0[k], lo, hi); float s0 = lo + hi;
            upk2(a1[k], lo, hi); float s1 = lo + hi;
            #pragma unroll
            for (int off = 16; off > 0; off >>= 1) {
                s0 += __shfl_xor_sync(0xffffffffu, s0, off);
                s1 += __shfl_xor_sync(0xffffffffu, s1, off);
            }
            if (lane == 0) {
                float* gp = &g_partial[(((size_t)b * S_CHUNKS + chunk) * K_DIM + k) * C_DIM];
                gp[c0] = s0 * inv;
                gp[c1] = s1 * inv;
            }
        }
    }
}

// ============================================================
// K2b: reduce partials -> class_feat, grouped filter GEMV (float4 loads).
// grid (19, 8), block 256.
// ============================================================
__global__ void __launch_bounds__(256) k_filters(
    const float* __restrict__ Wf, const float* __restrict__ bf)
{
    __shared__ float cf[C_DIM];
    int k = blockIdx.x, b = blockIdx.y;
    int tid = threadIdx.x;

    for (int c = tid; c < C_DIM; c += 256) {
        float sum = 0.0f;
        #pragma unroll
        for (int s = 0; s < S_CHUNKS; s++)
            sum += g_partial[(((size_t)b * S_CHUNKS + s) * K_DIM + k) * C_DIM + c];
        cf[c] = sum;
    }
    __syncthreads();

    int warp = tid >> 5, lane = tid & 31;
    const float4* cf4 = (const float4*)cf;
    for (int o = warp; o < C_DIM; o += 8) {
        const float4* wrow = (const float4*)(Wf + ((size_t)k * C_DIM + o) * C_DIM);
        float acc = 0.0f;
        #pragma unroll
        for (int j = 0; j < 4; j++) {
            float4 w = wrow[lane + 32 * j];
            float4 c = cf4[lane + 32 * j];
            acc += w.x * c.x + w.y * c.y + w.z * c.z + w.w * c.w;
        }
        #pragma unroll
        for (int off = 16; off > 0; off >>= 1)
            acc += __shfl_xor_sync(0xffffffffu, acc, off);
        if (lane == 0)
            g_filters[((size_t)b * K_DIM + k) * C_DIM + o] = acc + bf[k * C_DIM + o];
    }
}

// ============================================================
// K3: pred partial over half the channels (same shape as k_mask).
// ============================================================
__global__ void __launch_bounds__(256) k_pred(const float* __restrict__ x)
{
    __shared__ __align__(16) u64 wd[K_DIM * 256];
    int tid = threadIdx.x;
    int split = blockIdx.y, b = blockIdx.z;
    int c0 = split * 256;

    const float* fb = g_filters + (size_t)b * K_DIM * C_DIM;
    for (int i = tid; i < K_DIM * 256; i += 256) {
        float w = fb[(i >> 8) * C_DIM + c0 + (i & 255)];
        wd[i] = pk2(w, w);
    }
    __syncthreads();

    int p0 = blockIdx.x * 512 + tid * 2;
    const float* xb = x + ((size_t)b * C_DIM + c0) * HW + p0;

    u64 a[K_DIM];
    #pragma unroll
    for (int k = 0; k < K_DIM; k++) a[k] = 0ull;

    #pragma unroll 2
    for (int c = 0; c < 256; c += 2) {
        u64 x0 = *(const u64*)(xb + (size_t)(c + 0) * HW);
        u64 x1 = *(const u64*)(xb + (size_t)(c + 1) * HW);
        #pragma unroll
        for (int k = 0; k < K_DIM; k++) {
            ulonglong2 w = *(const ulonglong2*)&wd[k * 256 + c];
            a[k] = ffma2(w.x, x0, a[k]);
            a[k] = ffma2(w.y, x1, a[k]);
        }
    }

    float* gp = g_pre + (size_t)split * NHALF + ((size_t)b * K_DIM) * HW + p0;
    #pragma unroll
    for (int k = 0; k < K_DIM; k++)
        *(u64*)(gp + (size_t)k * HW) = a[k];
}

// ============================================================
// K3b: out = half0 + half1. float4 vectorized.
// ============================================================
__global__ void __launch_bounds__(256) k_comb(float* __restrict__ out)
{
    int i = blockIdx.x * 256 + threadIdx.x;
    float4 u = ((const float4*)g_pre)[i];
    float4 v = ((const float4*)(g_pre + NHALF))[i];
    ((float4*)out)[i] = make_float4(u.x + v.x, u.y + v.y, u.z + v.z, u.w + v.w);
}

// ============================================================
extern "C" void kernel_launch(void* const* d_in, const int* in_sizes, int n_in,
                              void* d_out, int out_size)
{
    const float* x  = (const float*)d_in[0];
    const float* Wm = (const float*)d_in[1];
    const float* bm = (const float*)d_in[2];
    const float* Wf = (const float*)d_in[3];
    const float* bf = (const float*)d_in[4];
    float* out = (float*)d_out;

    const int smem_pool = K_DIM * 512 * 8;   // 77824 B
    cudaFuncSetAttribute(k_pool, cudaFuncAttributeMaxDynamicSharedMemorySize, smem_pool);

    const int nv4 = NHALF / 4 / 256;         // 2432 blocks

    k_mask   <<<dim3(32, 2, B_DIM), 256>>>(x, Wm, bm);
    k_sig    <<<nv4, 256>>>(out);                              // mask -> d_out (scratch)
    k_pool   <<<dim3(S_CHUNKS, 2, B_DIM), 256, smem_pool>>>(x, out);
    k_filters<<<dim3(K_DIM, B_DIM), 256>>>(Wf, bf);
    k_pred   <<<dim3(32, 2, B_DIM), 256>>>(x);
    k_comb   <<<nv4, 256>>>(out);                              // final output
}

// round 8
// speedup vs baseline: 1.0239x; 1.0239x over previous
#include <cuda_runtime.h>

#define C_DIM 512
#define K_DIM 19
#define HW    16384
#define B_DIM 8
#define S_CHUNKS 32                    // pool chunks (512 positions each)
#define NHALF (B_DIM * K_DIM * HW)     // elements per csplit partial half

typedef unsigned long long u64;

// ---- f32x2 packed helpers ----
__device__ __forceinline__ u64 pk2(float lo, float hi) {
    u64 r; asm("mov.b64 %0, {%1, %2};" : "=l"(r) : "f"(lo), "f"(hi)); return r;
}
__device__ __forceinline__ void upk2(u64 v, float& lo, float& hi) {
    asm("mov.b64 {%0, %1}, %2;" : "=f"(lo), "=f"(hi) : "l"(v));
}
__device__ __forceinline__ u64 ffma2(u64 a, u64 b, u64 c) {
    u64 d; asm("fma.rn.f32x2 %0, %1, %2, %3;" : "=l"(d) : "l"(a), "l"(b), "l"(c)); return d;
}

// Static scratch
__device__ float g_pre[2 * NHALF];                            // csplit partials (19.9MB)
__device__ float g_partial[B_DIM * S_CHUNKS * K_DIM * C_DIM]; // pooling partials (10MB)
__device__ float g_cf[B_DIM * K_DIM * C_DIM];                 // class features
__device__ float g_filters[B_DIM * K_DIM * C_DIM];            // dynamic filters

// ============================================================
// K1: pre-mask partial over half the channels -> g_pre.
// grid (32 pos-tiles, 2 csplit, 8 b), 256 thr (3 CTAs/SM), 2 pos/thread.
// Weights pre-duplicated in smem; broadcast LDS.128 = 2 channels/load.
// ============================================================
__global__ void __launch_bounds__(256, 3) k_mask(
    const float* __restrict__ x, const float* __restrict__ Wm,
    const float* __restrict__ bm)
{
    __shared__ __align__(16) u64 wd[K_DIM * 256];   // 38912 B
    int tid = threadIdx.x;
    int split = blockIdx.y, b = blockIdx.z;
    int c0 = split * 256;

    for (int i = tid; i < K_DIM * 256; i += 256) {
        float w = Wm[(i >> 8) * C_DIM + c0 + (i & 255)];
        wd[i] = pk2(w, w);
    }
    __syncthreads();

    int p0 = blockIdx.x * 512 + tid * 2;
    const float* xb = x + ((size_t)b * C_DIM + c0) * HW + p0;

    u64 a[K_DIM];
    #pragma unroll
    for (int k = 0; k < K_DIM; k++) {
        float bv = (split == 0) ? __ldg(&bm[k]) : 0.0f;
        a[k] = pk2(bv, bv);
    }

    #pragma unroll 2
    for (int c = 0; c < 256; c += 2) {
        u64 x0 = *(const u64*)(xb + (size_t)(c + 0) * HW);
        u64 x1 = *(const u64*)(xb + (size_t)(c + 1) * HW);
        #pragma unroll
        for (int k = 0; k < K_DIM; k++) {
            ulonglong2 w = *(const ulonglong2*)&wd[k * 256 + c];
            a[k] = ffma2(w.x, x0, a[k]);
            a[k] = ffma2(w.y, x1, a[k]);
        }
    }

    float* gp = g_pre + (size_t)split * NHALF + ((size_t)b * K_DIM) * HW + p0;
    #pragma unroll
    for (int k = 0; k < K_DIM; k++)
        *(u64*)(gp + (size_t)k * HW) = a[k];
}

// ============================================================
// K2: pooling partials. grid (32 chunks, 8 b), 256 thr (8 warps).
// Chunk = 512 positions; mask = sigmoid(h0+h1) computed INLINE while
// staging pairs into smem. Warp covers 32 channel-pairs (ALL 256 pairs
// across 8 warps); one mask LDS.64 feeds 2 FFMA2s; shfl reduce.
// ============================================================
__global__ void __launch_bounds__(256, 2) k_pool(const float* __restrict__ x)
{
    __shared__ u64 m2[K_DIM * 256];   // 38912 B
    int tid = threadIdx.x;
    int chunk = blockIdx.x, b = blockIdx.y;
    int p0 = chunk * 512;

    // stage mask chunk: sigmoid(h0 + h1) as position pairs
    for (int i = tid; i < K_DIM * 256; i += 256) {
        int k = i >> 8, j = i & 255;
        size_t off = ((size_t)b * K_DIM + k) * HW + p0 + 2 * j;
        u64 h0 = *(const u64*)(g_pre + off);
        u64 h1 = *(const u64*)(g_pre + NHALF + off);
        float a0, a1, b0, b1;
        upk2(h0, a0, a1); upk2(h1, b0, b1);
        float s0 = 1.0f / (1.0f + __expf(-(a0 + b0)));
        float s1 = 1.0f / (1.0f + __expf(-(a1 + b1)));
        m2[i] = pk2(s0, s1);
    }
    __syncthreads();

    int warp = tid >> 5, lane = tid & 31;
    const float inv = 1.0f / (float)HW;
    const float* xbase = x + (size_t)b * C_DIM * HW + p0;

    for (int i = 0; i < 32; i++) {      // 32 iters x 8 warps = 256 pairs = 512 ch
        int cp = warp + 8 * i;
        int c0 = 2 * cp, c1 = c0 + 1;
        const float* x0p = xbase + (size_t)c0 * HW;
        const float* x1p = xbase + (size_t)c1 * HW;

        u64 a0[K_DIM], a1[K_DIM];
        #pragma unroll
        for (int k = 0; k < K_DIM; k++) { a0[k] = 0ull; a1[k] = 0ull; }

        #pragma unroll 2
        for (int t = 0; t < 8; t++) {   // 8 pair-steps cover 512 positions
            int idx = lane + 32 * t;
            u64 xv0 = *(const u64*)(x0p + 2 * idx);
            u64 xv1 = *(const u64*)(x1p + 2 * idx);
            #pragma unroll
            for (int k = 0; k < K_DIM; k++) {
                u64 m = m2[k * 256 + idx];
                a0[k] = ffma2(m, xv0, a0[k]);
                a1[k] = ffma2(m, xv1, a1[k]);
            }
        }

        #pragma unroll
        for (int k = 0; k < K_DIM; k++) {
            float lo, hi;
            upk2(a0[k], lo, hi); float s0 = lo + hi;
            upk2(a1[k], lo, hi); float s1 = lo + hi;
            #pragma unroll
            for (int off = 16; off > 0; off >>= 1) {
                s0 += __shfl_xor_sync(0xffffffffu, s0, off);
                s1 += __shfl_xor_sync(0xffffffffu, s1, off);
            }
            if (lane == 0) {
                float* gp = &g_partial[(((size_t)b * S_CHUNKS + chunk) * K_DIM + k) * C_DIM];
                gp[c0] = s0 * inv;
                gp[c1] = s1 * inv;
            }
        }
    }
}

// ============================================================
// K2b: reduce chunk partials -> class_feat. grid (19, 8), block 512.
// Thread owns one channel; 32 serial chunk loads, unrolled for MLP.
// ============================================================
__global__ void __launch_bounds__(512) k_cf()
{
    int k = blockIdx.x, b = blockIdx.y;
    int c = threadIdx.x;
    const float* gp = g_partial + ((size_t)b * S_CHUNKS * K_DIM + k) * C_DIM + c;
    float sum = 0.0f;
    #pragma unroll 8
    for (int s = 0; s < S_CHUNKS; s++)
        sum += gp[(size_t)s * K_DIM * C_DIM];
    g_cf[((size_t)b * K_DIM + k) * C_DIM + c] = sum;
}

// ============================================================
// K2c: filters[b,k,o] = Wf[k,o,:] . cf[b,k,:] + bf[k,o].
// grid (19, 4 osplit, 8 b), block 128 (4 warps).
// cf held in registers (4 float4/lane); warp processes 4 o concurrently
// -> 16 LDG.128 in flight -> DRAM-latency covered.
// ============================================================
__global__ void __launch_bounds__(128) k_filters(
    const float* __restrict__ Wf, const float* __restrict__ bf)
{
    int k = blockIdx.x, osplit = blockIdx.y, b = blockIdx.z;
    int warp = threadIdx.x >> 5, lane = threadIdx.x & 31;

    // cf into registers (each warp loads the same 512 floats; L2-hot)
    const float4* cf4 = (const float4*)(g_cf + ((size_t)b * K_DIM + k) * C_DIM);
    float4 cfr[4];
    #pragma unroll
    for (int j = 0; j < 4; j++) cfr[j] = __ldg(&cf4[lane + 32 * j]);

    int obase = osplit * 128 + warp * 32;      // 32 o per warp, 8 groups of 4
    for (int g = 0; g < 8; g++) {
        int o = obase + 4 * g;
        const float4* w0 = (const float4*)(Wf + ((size_t)k * C_DIM + o + 0) * C_DIM);
        const float4* w1 = (const float4*)(Wf + ((size_t)k * C_DIM + o + 1) * C_DIM);
        const float4* w2 = (const float4*)(Wf + ((size_t)k * C_DIM + o + 2) * C_DIM);
        const float4* w3 = (const float4*)(Wf + ((size_t)k * C_DIM + o + 3) * C_DIM);

        float acc0 = 0.f, acc1 = 0.f, acc2 = 0.f, acc3 = 0.f;
        #pragma unroll
        for (int j = 0; j < 4; j++) {
            int idx = lane + 32 * j;
            float4 a = w0[idx], bb = w1[idx], cc = w2[idx], dd = w3[idx];
            float4 f = cfr[j];
            acc0 += a.x * f.x + a.y * f.y + a.z * f.z + a.w * f.w;
            acc1 += bb.x * f.x + bb.y * f.y + bb.z * f.z + bb.w * f.w;
            acc2 += cc.x * f.x + cc.y * f.y + cc.z * f.z + cc.w * f.w;
            acc3 += dd.x * f.x + dd.y * f.y + dd.z * f.z + dd.w * f.w;
        }
        #pragma unroll
        for (int off = 16; off > 0; off >>= 1) {
            acc0 += __shfl_xor_sync(0xffffffffu, acc0, off);
            acc1 += __shfl_xor_sync(0xffffffffu, acc1, off);
            acc2 += __shfl_xor_sync(0xffffffffu, acc2, off);
            acc3 += __shfl_xor_sync(0xffffffffu, acc3, off);
        }
        if (lane < 4) {
            float v = (lane == 0) ? acc0 : (lane == 1) ? acc1 : (lane == 2) ? acc2 : acc3;
            g_filters[((size_t)b * K_DIM + k) * C_DIM + o + lane] =
                v + bf[k * C_DIM + o + lane];
        }
    }
}

// ============================================================
// K3: pred partial over half the channels (same shape as k_mask).
// ============================================================
__global__ void __launch_bounds__(256, 3) k_pred(const float* __restrict__ x)
{
    __shared__ __align__(16) u64 wd[K_DIM * 256];
    int tid = threadIdx.x;
    int split = blockIdx.y, b = blockIdx.z;
    int c0 = split * 256;

    const float* fb = g_filters + (size_t)b * K_DIM * C_DIM;
    for (int i = tid; i < K_DIM * 256; i += 256) {
        float w = fb[(i >> 8) * C_DIM + c0 + (i & 255)];
        wd[i] = pk2(w, w);
    }
    __syncthreads();

    int p0 = blockIdx.x * 512 + tid * 2;
    const float* xb = x + ((size_t)b * C_DIM + c0) * HW + p0;

    u64 a[K_DIM];
    #pragma unroll
    for (int k = 0; k < K_DIM; k++) a[k] = 0ull;

    #pragma unroll 2
    for (int c = 0; c < 256; c += 2) {
        u64 x0 = *(const u64*)(xb + (size_t)(c + 0) * HW);
        u64 x1 = *(const u64*)(xb + (size_t)(c + 1) * HW);
        #pragma unroll
        for (int k = 0; k < K_DIM; k++) {
            ulonglong2 w = *(const ulonglong2*)&wd[k * 256 + c];
            a[k] = ffma2(w.x, x0, a[k]);
            a[k] = ffma2(w.y, x1, a[k]);
        }
    }

    float* gp = g_pre + (size_t)split * NHALF + ((size_t)b * K_DIM) * HW + p0;
    #pragma unroll
    for (int k = 0; k < K_DIM; k++)
        *(u64*)(gp + (size_t)k * HW) = a[k];
}

// ============================================================
// K3b: out = half0 + half1. float4 vectorized. grid 2432 x 256.
// ============================================================
__global__ void __launch_bounds__(256) k_comb(float* __restrict__ out)
{
    int i = blockIdx.x * 256 + threadIdx.x;
    float4 u = ((const float4*)g_pre)[i];
    float4 v = ((const float4*)(g_pre + NHALF))[i];
    ((float4*)out)[i] = make_float4(u.x + v.x, u.y + v.y, u.z + v.z, u.w + v.w);
}

// ============================================================
extern "C" void kernel_launch(void* const* d_in, const int* in_sizes, int n_in,
                              void* d_out, int out_size)
{
    const float* x  = (const float*)d_in[0];
    const float* Wm = (const float*)d_in[1];
    const float* bm = (const float*)d_in[2];
    const float* Wf = (const float*)d_in[3];
    const float* bf = (const float*)d_in[4];
    float* out = (float*)d_out;

    const int nv4 = NHALF / 4 / 256;         // 2432 blocks

    k_mask   <<<dim3(32, 2, B_DIM), 256>>>(x, Wm, bm);
    k_pool   <<<dim3(S_CHUNKS, B_DIM), 256>>>(x);
    k_cf     <<<dim3(K_DIM, B_DIM), 512>>>();
    k_filters<<<dim3(K_DIM, 4, B_DIM), 128>>>(Wf, bf);
    k_pred   <<<dim3(32, 2, B_DIM), 256>>>(x);
    k_comb   <<<nv4, 256>>>(out);
}

// round 10
// speedup vs baseline: 1.2678x; 1.2382x over previous
#include <cuda_runtime.h>

#define C_DIM 512
#define K_DIM 19
#define HW    16384
#define B_DIM 8
#define S_CHUNKS 32                    // pool chunks (512 positions each)
#define NHALF (B_DIM * K_DIM * HW)     // elements per csplit partial half

typedef unsigned long long u64;

// ---- f32x2 packed helpers ----
__device__ __forceinline__ u64 pk2(float lo, float hi) {
    u64 r; asm("mov.b64 %0, {%1, %2};" : "=l"(r) : "f"(lo), "f"(hi)); return r;
}
__device__ __forceinline__ void upk2(u64 v, float& lo, float& hi) {
    asm("mov.b64 {%0, %1}, %2;" : "=f"(lo), "=f"(hi) : "l"(v));
}
__device__ __forceinline__ u64 ffma2(u64 a, u64 b, u64 c) {
    u64 d; asm("fma.rn.f32x2 %0, %1, %2, %3;" : "=l"(d) : "l"(a), "l"(b), "l"(c)); return d;
}

// Static scratch
__device__ float g_pre[2 * NHALF];                            // csplit partials (19.9MB)
__device__ float g_partial[B_DIM * S_CHUNKS * K_DIM * C_DIM]; // pooling partials (10MB)
__device__ float g_cf[B_DIM * K_DIM * C_DIM];                 // class features
__device__ float g_filters[B_DIM * K_DIM * C_DIM];            // dynamic filters

// ============================================================
// K1: pre-mask partial over half the channels -> g_pre.
// grid (32 pos-tiles, 2 csplit, 8 b), 128 thr, 4 consecutive pos/thread
// (one LDG.128 per channel). Weights dup'd in smem; one broadcast
// LDS.128 (2 channels) feeds 4 FFMA2 -> fma-bound, not crossbar-bound.
// (128,4): exactly 128 regs -> 4 CTAs/SM = 16 warps.
// ============================================================
__global__ void __launch_bounds__(128, 4) k_mask(
    const float* __restrict__ x, const float* __restrict__ Wm,
    const float* __restrict__ bm)
{
    __shared__ __align__(16) u64 wd[K_DIM * 256];   // dup pairs, 38912 B
    int tid = threadIdx.x;
    int split = blockIdx.y, b = blockIdx.z;
    int c0 = split * 256;

    for (int i = tid; i < K_DIM * 256; i += 128) {
        float w = Wm[(i >> 8) * C_DIM + c0 + (i & 255)];
        wd[i] = pk2(w, w);
    }
    __syncthreads();

    int p0 = blockIdx.x * 512 + tid * 4;
    const float* xb = x + ((size_t)b * C_DIM + c0) * HW + p0;

    u64 a0[K_DIM], a1[K_DIM];   // pair(pos0,1), pair(pos2,3)
    #pragma unroll
    for (int k = 0; k < K_DIM; k++) {
        float bv = (split == 0) ? __ldg(&bm[k]) : 0.0f;
        a0[k] = pk2(bv, bv); a1[k] = a0[k];
    }

    #pragma unroll 1
    for (int c = 0; c < 256; c += 2) {
        ulonglong2 xa = *(const ulonglong2*)(xb + (size_t)(c + 0) * HW);  // 4 pos, ch c
        ulonglong2 xc = *(const ulonglong2*)(xb + (size_t)(c + 1) * HW);  // 4 pos, ch c+1
        #pragma unroll
        for (int k = 0; k < K_DIM; k++) {
            ulonglong2 w = *(const ulonglong2*)&wd[k * 256 + c];  // bcast LDS.128: 2 ch dup'd
            a0[k] = ffma2(w.x, xa.x, a0[k]);
            a1[k] = ffma2(w.x, xa.y, a1[k]);
            a0[k] = ffma2(w.y, xc.x, a0[k]);
            a1[k] = ffma2(w.y, xc.y, a1[k]);
        }
    }

    float* gp = g_pre + (size_t)split * NHALF + ((size_t)b * K_DIM) * HW + p0;
    #pragma unroll
    for (int k = 0; k < K_DIM; k++) {
        ulonglong2 v; v.x = a0[k]; v.y = a1[k];
        *(ulonglong2*)(gp + (size_t)k * HW) = v;
    }
}

// ============================================================
// K2: pooling partials. grid (32 chunks, 8 b), 256 thr (8 warps).
// Chunk = 512 positions; mask = sigmoid(h0+h1) computed INLINE while
// staging pairs into smem. Warp covers 32 channel-pairs; one mask
// LDS.64 feeds 2 FFMA2s; shfl reduce.
// ============================================================
__global__ void __launch_bounds__(256, 2) k_pool(const float* __restrict__ x)
{
    __shared__ u64 m2[K_DIM * 256];   // 38912 B
    int tid = threadIdx.x;
    int chunk = blockIdx.x, b = blockIdx.y;
    int p0 = chunk * 512;

    // stage mask chunk: sigmoid(h0 + h1) as position pairs
    for (int i = tid; i < K_DIM * 256; i += 256) {
        int k = i >> 8, j = i & 255;
        size_t off = ((size_t)b * K_DIM + k) * HW + p0 + 2 * j;
        u64 h0 = *(const u64*)(g_pre + off);
        u64 h1 = *(const u64*)(g_pre + NHALF + off);
        float a0, a1, b0, b1;
        upk2(h0, a0, a1); upk2(h1, b0, b1);
        float s0 = 1.0f / (1.0f + __expf(-(a0 + b0)));
        float s1 = 1.0f / (1.0f + __expf(-(a1 + b1)));
        m2[i] = pk2(s0, s1);
    }
    __syncthreads();

    int warp = tid >> 5, lane = tid & 31;
    const float inv = 1.0f / (float)HW;
    const float* xbase = x + (size_t)b * C_DIM * HW + p0;

    for (int i = 0; i < 32; i++) {      // 32 iters x 8 warps = 256 pairs = 512 ch
        int cp = warp + 8 * i;
        int c0 = 2 * cp, c1 = c0 + 1;
        const float* x0p = xbase + (size_t)c0 * HW;
        const float* x1p = xbase + (size_t)c1 * HW;

        u64 a0[K_DIM], a1[K_DIM];
        #pragma unroll
        for (int k = 0; k < K_DIM; k++) { a0[k] = 0ull; a1[k] = 0ull; }

        #pragma unroll 2
        for (int t = 0; t < 8; t++) {   // 8 pair-steps cover 512 positions
            int idx = lane + 32 * t;
            u64 xv0 = *(const u64*)(x0p + 2 * idx);
            u64 xv1 = *(const u64*)(x1p + 2 * idx);
            #pragma unroll
            for (int k = 0; k < K_DIM; k++) {
                u64 m = m2[k * 256 + idx];
                a0[k] = ffma2(m, xv0, a0[k]);
                a1[k] = ffma2(m, xv1, a1[k]);
            }
        }

        #pragma unroll
        for (int k = 0; k < K_DIM; k++) {
            float lo, hi;
            upk2(a0[k], lo, hi); float s0 = lo + hi;
            upk2(a1[k], lo, hi); float s1 = lo + hi;
            #pragma unroll
            for (int off = 16; off > 0; off >>= 1) {
                s0 += __shfl_xor_sync(0xffffffffu, s0, off);
                s1 += __shfl_xor_sync(0xffffffffu, s1, off);
            }
            if (lane == 0) {
                float* gp = &g_partial[(((size_t)b * S_CHUNKS + chunk) * K_DIM + k) * C_DIM];
                gp[c0] = s0 * inv;
                gp[c1] = s1 * inv;
            }
        }
    }
}

// ============================================================
// K2b: reduce chunk partials -> class_feat. grid (19, 8), block 512.
// ============================================================
__global__ void __launch_bounds__(512) k_cf()
{
    int k = blockIdx.x, b = blockIdx.y;
    int c = threadIdx.x;
    const float* gp = g_partial + ((size_t)b * S_CHUNKS * K_DIM + k) * C_DIM + c;
    float sum = 0.0f;
    #pragma unroll 8
    for (int s = 0; s < S_CHUNKS; s++)
        sum += gp[(size_t)s * K_DIM * C_DIM];
    g_cf[((size_t)b * K_DIM + k) * C_DIM + c] = sum;
}

// ============================================================
// K2c: filters GEMV. grid (19, 8 osplit, 8 b) = 1216 CTAs, block 128.
// 16 o per warp (4 groups of 4 concurrent rows) -> 8.2 CTAs/SM,
// shfl-tree bubbles hidden by warp supply.
// ============================================================
__global__ void __launch_bounds__(128) k_filters(
    const float* __restrict__ Wf, const float* __restrict__ bf)
{
    int k = blockIdx.x, osplit = blockIdx.y, b = blockIdx.z;
    int warp = threadIdx.x >> 5, lane = threadIdx.x & 31;

    const float4* cf4 = (const float4*)(g_cf + ((size_t)b * K_DIM + k) * C_DIM);
    float4 cfr[4];
    #pragma unroll
    for (int j = 0; j < 4; j++) cfr[j] = __ldg(&cf4[lane + 32 * j]);

    int obase = osplit * 64 + warp * 16;       // 16 o per warp, 4 groups of 4
    for (int g = 0; g < 4; g++) {
        int o = obase + 4 * g;
        const float4* w0 = (const float4*)(Wf + ((size_t)k * C_DIM + o + 0) * C_DIM);
        const float4* w1 = (const float4*)(Wf + ((size_t)k * C_DIM + o + 1) * C_DIM);
        const float4* w2 = (const float4*)(Wf + ((size_t)k * C_DIM + o + 2) * C_DIM);
        const float4* w3 = (const float4*)(Wf + ((size_t)k * C_DIM + o + 3) * C_DIM);

        float acc0 = 0.f, acc1 = 0.f, acc2 = 0.f, acc3 = 0.f;
        #pragma unroll
        for (int j = 0; j < 4; j++) {
            int idx = lane + 32 * j;
            float4 a = w0[idx], bb = w1[idx], cc = w2[idx], dd = w3[idx];
            float4 f = cfr[j];
            acc0 += a.x * f.x + a.y * f.y + a.z * f.z + a.w * f.w;
            acc1 += bb.x * f.x + bb.y * f.y + bb.z * f.z + bb.w * f.w;
            acc2 += cc.x * f.x + cc.y * f.y + cc.z * f.z + cc.w * f.w;
            acc3 += dd.x * f.x + dd.y * f.y + dd.z * f.z + dd.w * f.w;
        }
        #pragma unroll
        for (int off = 16; off > 0; off >>= 1) {
            acc0 += __shfl_xor_sync(0xffffffffu, acc0, off);
            acc1 += __shfl_xor_sync(0xffffffffu, acc1, off);
            acc2 += __shfl_xor_sync(0xffffffffu, acc2, off);
            acc3 += __shfl_xor_sync(0xffffffffu, acc3, off);
        }
        if (lane < 4) {
            float v = (lane == 0) ? acc0 : (lane == 1) ? acc1 : (lane == 2) ? acc2 : acc3;
            g_filters[((size_t)b * K_DIM + k) * C_DIM + o + lane] =
                v + bf[k * C_DIM + o + lane];
        }
    }
}

// ============================================================
// K3: pred partial over half the channels (same shape as k_mask).
// ============================================================
__global__ void __launch_bounds__(128, 4) k_pred(const float* __restrict__ x)
{
    __shared__ __align__(16) u64 wd[K_DIM * 256];
    int tid = threadIdx.x;
    int split = blockIdx.y, b = blockIdx.z;
    int c0 = split * 256;

    const float* fb = g_filters + (size_t)b * K_DIM * C_DIM;
    for (int i = tid; i < K_DIM * 256; i += 128) {
        float w = fb[(i >> 8) * C_DIM + c0 + (i & 255)];
        wd[i] = pk2(w, w);
    }
    __syncthreads();

    int p0 = blockIdx.x * 512 + tid * 4;
    const float* xb = x + ((size_t)b * C_DIM + c0) * HW + p0;

    u64 a0[K_DIM], a1[K_DIM];
    #pragma unroll
    for (int k = 0; k < K_DIM; k++) { a0[k] = 0ull; a1[k] = 0ull; }

    #pragma unroll 1
    for (int c = 0; c < 256; c += 2) {
        ulonglong2 xa = *(const ulonglong2*)(xb + (size_t)(c + 0) * HW);
        ulonglong2 xc = *(const ulonglong2*)(xb + (size_t)(c + 1) * HW);
        #pragma unroll
        for (int k = 0; k < K_DIM; k++) {
            ulonglong2 w = *(const ulonglong2*)&wd[k * 256 + c];
            a0[k] = ffma2(w.x, xa.x, a0[k]);
            a1[k] = ffma2(w.x, xa.y, a1[k]);
            a0[k] = ffma2(w.y, xc.x, a0[k]);
            a1[k] = ffma2(w.y, xc.y, a1[k]);
        }
    }

    float* gp = g_pre + (size_t)split * NHALF + ((size_t)b * K_DIM) * HW + p0;
    #pragma unroll
    for (int k = 0; k < K_DIM; k++) {
        ulonglong2 v; v.x = a0[k]; v.y = a1[k];
        *(ulonglong2*)(gp + (size_t)k * HW) = v;
    }
}

// ============================================================
// K3b: out = half0 + half1. float4 vectorized. grid 2432 x 256.
// ============================================================
__global__ void __launch_bounds__(256) k_comb(float* __restrict__ out)
{
    int i = blockIdx.x * 256 + threadIdx.x;
    float4 u = ((const float4*)g_pre)[i];
    float4 v = ((const float4*)(g_pre + NHALF))[i];
    ((float4*)out)[i] = make_float4(u.x + v.x, u.y + v.y, u.z + v.z, u.w + v.w);
}

// ============================================================
extern "C" void kernel_launch(void* const* d_in, const int* in_sizes, int n_in,
                              void* d_out, int out_size)
{
    const float* x  = (const float*)d_in[0];
    const float* Wm = (const float*)d_in[1];
    const float* bm = (const float*)d_in[2];
    const float* Wf = (const float*)d_in[3];
    const float* bf = (const float*)d_in[4];
    float* out = (float*)d_out;

    const int nv4 = NHALF / 4 / 256;         // 2432 blocks

    k_mask   <<<dim3(32, 2, B_DIM), 128>>>(x, Wm, bm);
    k_pool   <<<dim3(S_CHUNKS, B_DIM), 256>>>(x);
    k_cf     <<<dim3(K_DIM, B_DIM), 512>>>();
    k_filters<<<dim3(K_DIM, 8, B_DIM), 128>>>(Wf, bf);
    k_pred   <<<dim3(32, 2, B_DIM), 128>>>(x);
    k_comb   <<<nv4, 256>>>(out);
}

// round 11
// speedup vs baseline: 1.4699x; 1.1594x over previous
#include <cuda_runtime.h>

#define C_DIM 512
#define K_DIM 19
#define K_PAD 20                       // padded class dim for pool ksplit
#define HW    16384
#define B_DIM 8
#define S_CHUNKS 16                    // pool chunks (1024 positions each)
#define NHALF (B_DIM * K_DIM * HW)     // elements per csplit partial half

typedef unsigned long long u64;

// ---- f32x2 packed helpers ----
__device__ __forceinline__ u64 pk2(float lo, float hi) {
    u64 r; asm("mov.b64 %0, {%1, %2};" : "=l"(r) : "f"(lo), "f"(hi)); return r;
}
__device__ __forceinline__ void upk2(u64 v, float& lo, float& hi) {
    asm("mov.b64 {%0, %1}, %2;" : "=f"(lo), "=f"(hi) : "l"(v));
}
__device__ __forceinline__ u64 ffma2(u64 a, u64 b, u64 c) {
    u64 d; asm("fma.rn.f32x2 %0, %1, %2, %3;" : "=l"(d) : "l"(a), "l"(b), "l"(c)); return d;
}

// Static scratch
__device__ float g_pre[2 * NHALF];                             // csplit partials (19.9MB)
__device__ float g_partial[B_DIM * S_CHUNKS * K_PAD * C_DIM];  // pooling partials (5.2MB)
__device__ float g_cf[B_DIM * K_DIM * C_DIM];                  // class features
__device__ float g_filters[B_DIM * K_DIM * C_DIM];             // dynamic filters

// ============================================================
// K1: pre-mask partial over half the channels -> g_pre.
// grid (32 pos-tiles, 2 csplit, 8 b), 128 thr, 4 pos/thread.
// Dup'd-pair weights in smem (broadcast LDS.128 = 2 ch, 4 FFMA2/wf).
// Manual x double-buffer -> MLP 4 on the gmem stream.
// ============================================================
__global__ void __launch_bounds__(128, 4) k_mask(
    const float* __restrict__ x, const float* __restrict__ Wm,
    const float* __restrict__ bm)
{
    __shared__ __align__(16) u64 wd[K_DIM * 256];   // 38912 B
    int tid = threadIdx.x;
    int split = blockIdx.y, b = blockIdx.z;
    int c0 = split * 256;

    for (int i = tid; i < K_DIM * 256; i += 128) {
        float w = Wm[(i >> 8) * C_DIM + c0 + (i & 255)];
        wd[i] = pk2(w, w);
    }
    __syncthreads();

    int p0 = blockIdx.x * 512 + tid * 4;
    const float* xb = x + ((size_t)b * C_DIM + c0) * HW + p0;

    u64 a0[K_DIM], a1[K_DIM];
    #pragma unroll
    for (int k = 0; k < K_DIM; k++) {
        float bv = (split == 0) ? __ldg(&bm[k]) : 0.0f;
        a0[k] = pk2(bv, bv); a1[k] = a0[k];
    }

    ulonglong2 xa = *(const ulonglong2*)(xb + (size_t)0 * HW);
    ulonglong2 xc = *(const ulonglong2*)(xb + (size_t)1 * HW);

    #pragma unroll 1
    for (int c = 0; c < 256; c += 2) {
        int cn = (c < 254) ? c + 2 : 254;          // clamped prefetch
        ulonglong2 xa_n = *(const ulonglong2*)(xb + (size_t)(cn + 0) * HW);
        ulonglong2 xc_n = *(const ulonglong2*)(xb + (size_t)(cn + 1) * HW);
        #pragma unroll
        for (int k = 0; k < K_DIM; k++) {
            ulonglong2 w = *(const ulonglong2*)&wd[k * 256 + c];
            a0[k] = ffma2(w.x, xa.x, a0[k]);
            a1[k] = ffma2(w.x, xa.y, a1[k]);
            a0[k] = ffma2(w.y, xc.x, a0[k]);
            a1[k] = ffma2(w.y, xc.y, a1[k]);
        }
        xa = xa_n; xc = xc_n;
    }

    float* gp = g_pre + (size_t)split * NHALF + ((size_t)b * K_DIM) * HW + p0;
    #pragma unroll
    for (int k = 0; k < K_DIM; k++) {
        ulonglong2 v; v.x = a0[k]; v.y = a1[k];
        *(ulonglong2*)(gp + (size_t)k * HW) = v;
    }
}

// ============================================================
// K2: pooling partials. grid (2 ksplit, 16 chunks, 8 b), 256 thr.
// Each CTA: 10 classes (padded; k=19 row is zeros), ALL 512 channels,
// chunk = 1024 positions. Lane owns a channel-QUAD: one mask LDS.64
// feeds 4 FFMA2 -> crossbar:fma balanced. Sigmoid fused into staging.
// ============================================================
__global__ void __launch_bounds__(256, 2) k_pool(const float* __restrict__ x)
{
    __shared__ u64 m2[10 * 512];   // 40960 B: this ksplit's mask rows, pos pairs
    int tid = threadIdx.x;
    int ksplit = blockIdx.x, chunk = blockIdx.y, b = blockIdx.z;
    int p0 = chunk * 1024;
    int K0 = ksplit * 10;

    // stage mask rows K0..K0+9: sigmoid(h0+h1); padded row k=19 -> 0
    for (int i = tid; i < 10 * 512; i += 256) {
        int kh = i >> 9, j = i & 511;
        int k = K0 + kh;
        if (k < K_DIM) {
            size_t off = ((size_t)b * K_DIM + k) * HW + p0 + 2 * j;
            u64 h0 = *(const u64*)(g_pre + off);
            u64 h1 = *(const u64*)(g_pre + NHALF + off);
            float a0, a1, b0, b1;
            upk2(h0, a0, a1); upk2(h1, b0, b1);
            float s0 = 1.0f / (1.0f + __expf(-(a0 + b0)));
            float s1 = 1.0f / (1.0f + __expf(-(a1 + b1)));
            m2[i] = pk2(s0, s1);
        } else {
            m2[i] = 0ull;
        }
    }
    __syncthreads();

    int warp = tid >> 5, lane = tid & 31;
    const float inv = 1.0f / (float)HW;
    const float* xbase = x + (size_t)b * C_DIM * HW + p0;

    for (int i = 0; i < 16; i++) {          // 8 warps x 16 = 128 quads = 512 ch
        int cbase = 4 * (warp + 8 * i);
        const float* xp0 = xbase + (size_t)(cbase + 0) * HW;
        const float* xp1 = xbase + (size_t)(cbase + 1) * HW;
        const float* xp2 = xbase + (size_t)(cbase + 2) * HW;
        const float* xp3 = xbase + (size_t)(cbase + 3) * HW;

        u64 a[40];
        #pragma unroll
        for (int j = 0; j < 40; j++) a[j] = 0ull;

        #pragma unroll 2
        for (int t = 0; t < 16; t++) {      // 16 pair-steps x 32 lanes = 512 pairs
            int idx = lane + 32 * t;
            u64 xv0 = *(const u64*)(xp0 + 2 * idx);
            u64 xv1 = *(const u64*)(xp1 + 2 * idx);
            u64 xv2 = *(const u64*)(xp2 + 2 * idx);
            u64 xv3 = *(const u64*)(xp3 + 2 * idx);
            #pragma unroll
            for (int kh = 0; kh < 10; kh++) {
                u64 m = m2[kh * 512 + idx];
                a[kh * 4 + 0] = ffma2(m, xv0, a[kh * 4 + 0]);
                a[kh * 4 + 1] = ffma2(m, xv1, a[kh * 4 + 1]);
                a[kh * 4 + 2] = ffma2(m, xv2, a[kh * 4 + 2]);
                a[kh * 4 + 3] = ffma2(m, xv3, a[kh * 4 + 3]);
            }
        }

        #pragma unroll
        for (int kh = 0; kh < 10; kh++) {
            float s[4];
            #pragma unroll
            for (int j = 0; j < 4; j++) {
                float lo, hi; upk2(a[kh * 4 + j], lo, hi); s[j] = lo + hi;
            }
            #pragma unroll
            for (int off = 16; off > 0; off >>= 1) {
                #pragma unroll
                for (int j = 0; j < 4; j++)
                    s[j] += __shfl_xor_sync(0xffffffffu, s[j], off);
            }
            if (lane == 0) {
                float* gp = &g_partial[(((size_t)b * S_CHUNKS + chunk) * K_PAD + K0 + kh) * C_DIM + cbase];
                gp[0] = s[0] * inv; gp[1] = s[1] * inv;
                gp[2] = s[2] * inv; gp[3] = s[3] * inv;
            }
        }
    }
}

// ============================================================
// K2b: reduce chunk partials -> class_feat. grid (19, 8), block 512.
// ============================================================
__global__ void __launch_bounds__(512) k_cf()
{
    int k = blockIdx.x, b = blockIdx.y;
    int c = threadIdx.x;
    const float* gp = g_partial + ((size_t)b * S_CHUNKS * K_PAD + k) * C_DIM + c;
    float sum = 0.0f;
    #pragma unroll 8
    for (int s = 0; s < S_CHUNKS; s++)
        sum += gp[(size_t)s * K_PAD * C_DIM];
    g_cf[((size_t)b * K_DIM + k) * C_DIM + c] = sum;
}

// ============================================================
// K2c: filters GEMV. grid (19, 8 osplit, 8 b) = 1216 CTAs, block 128.
// ============================================================
__global__ void __launch_bounds__(128) k_filters(
    const float* __restrict__ Wf, const float* __restrict__ bf)
{
    int k = blockIdx.x, osplit = blockIdx.y, b = blockIdx.z;
    int warp = threadIdx.x >> 5, lane = threadIdx.x & 31;

    const float4* cf4 = (const float4*)(g_cf + ((size_t)b * K_DIM + k) * C_DIM);
    float4 cfr[4];
    #pragma unroll
    for (int j = 0; j < 4; j++) cfr[j] = __ldg(&cf4[lane + 32 * j]);

    int obase = osplit * 64 + warp * 16;
    for (int g = 0; g < 4; g++) {
        int o = obase + 4 * g;
        const float4* w0 = (const float4*)(Wf + ((size_t)k * C_DIM + o + 0) * C_DIM);
        const float4* w1 = (const float4*)(Wf + ((size_t)k * C_DIM + o + 1) * C_DIM);
        const float4* w2 = (const float4*)(Wf + ((size_t)k * C_DIM + o + 2) * C_DIM);
        const float4* w3 = (const float4*)(Wf + ((size_t)k * C_DIM + o + 3) * C_DIM);

        float acc0 = 0.f, acc1 = 0.f, acc2 = 0.f, acc3 = 0.f;
        #pragma unroll
        for (int j = 0; j < 4; j++) {
            int idx = lane + 32 * j;
            float4 a = w0[idx], bb = w1[idx], cc = w2[idx], dd = w3[idx];
            float4 f = cfr[j];
            acc0 += a.x * f.x + a.y * f.y + a.z * f.z + a.w * f.w;
            acc1 += bb.x * f.x + bb.y * f.y + bb.z * f.z + bb.w * f.w;
            acc2 += cc.x * f.x + cc.y * f.y + cc.z * f.z + cc.w * f.w;
            acc3 += dd.x * f.x + dd.y * f.y + dd.z * f.z + dd.w * f.w;
        }
        #pragma unroll
        for (int off = 16; off > 0; off >>= 1) {
            acc0 += __shfl_xor_sync(0xffffffffu, acc0, off);
            acc1 += __shfl_xor_sync(0xffffffffu, acc1, off);
            acc2 += __shfl_xor_sync(0xffffffffu, acc2, off);
            acc3 += __shfl_xor_sync(0xffffffffu, acc3, off);
        }
        if (lane < 4) {
            float v = (lane == 0) ? acc0 : (lane == 1) ? acc1 : (lane == 2) ? acc2 : acc3;
            g_filters[((size_t)b * K_DIM + k) * C_DIM + o + lane] =
                v + bf[k * C_DIM + o + lane];
        }
    }
}

// ============================================================
// K3: pred partial over half the channels (same shape as k_mask).
// ============================================================
__global__ void __launch_bounds__(128, 4) k_pred(const float* __restrict__ x)
{
    __shared__ __align__(16) u64 wd[K_DIM * 256];
    int tid = threadIdx.x;
    int split = blockIdx.y, b = blockIdx.z;
    int c0 = split * 256;

    const float* fb = g_filters + (size_t)b * K_DIM * C_DIM;
    for (int i = tid; i < K_DIM * 256; i += 128) {
        float w = fb[(i >> 8) * C_DIM + c0 + (i & 255)];
        wd[i] = pk2(w, w);
    }
    __syncthreads();

    int p0 = blockIdx.x * 512 + tid * 4;
    const float* xb = x + ((size_t)b * C_DIM + c0) * HW + p0;

    u64 a0[K_DIM], a1[K_DIM];
    #pragma unroll
    for (int k = 0; k < K_DIM; k++) { a0[k] = 0ull; a1[k] = 0ull; }

    ulonglong2 xa = *(const ulonglong2*)(xb + (size_t)0 * HW);
    ulonglong2 xc = *(const ulonglong2*)(xb + (size_t)1 * HW);

    #pragma unroll 1
    for (int c = 0; c < 256; c += 2) {
        int cn = (c < 254) ? c + 2 : 254;
        ulonglong2 xa_n = *(const ulonglong2*)(xb + (size_t)(cn + 0) * HW);
        ulonglong2 xc_n = *(const ulonglong2*)(xb + (size_t)(cn + 1) * HW);
        #pragma unroll
        for (int k = 0; k < K_DIM; k++) {
            ulonglong2 w = *(const ulonglong2*)&wd[k * 256 + c];
            a0[k] = ffma2(w.x, xa.x, a0[k]);
            a1[k] = ffma2(w.x, xa.y, a1[k]);
            a0[k] = ffma2(w.y, xc.x, a0[k]);
            a1[k] = ffma2(w.y, xc.y, a1[k]);
        }
        xa = xa_n; xc = xc_n;
    }

    float* gp = g_pre + (size_t)split * NHALF + ((size_t)b * K_DIM) * HW + p0;
    #pragma unroll
    for (int k = 0; k < K_DIM; k++) {
        ulonglong2 v; v.x = a0[k]; v.y = a1[k];
        *(ulonglong2*)(gp + (size_t)k * HW) = v;
    }
}

// ============================================================
// K3b: out = half0 + half1. float4 vectorized. grid 2432 x 256.
// ============================================================
__global__ void __launch_bounds__(256) k_comb(float* __restrict__ out)
{
    int i = blockIdx.x * 256 + threadIdx.x;
    float4 u = ((const float4*)g_pre)[i];
    float4 v = ((const float4*)(g_pre + NHALF))[i];
    ((float4*)out)[i] = make_float4(u.x + v.x, u.y + v.y, u.z + v.z, u.w + v.w);
}

// ============================================================
extern "C" void kernel_launch(void* const* d_in, const int* in_sizes, int n_in,
                              void* d_out, int out_size)
{
    const float* x  = (const float*)d_in[0];
    const float* Wm = (const float*)d_in[1];
    const float* bm = (const float*)d_in[2];
    const float* Wf = (const float*)d_in[3];
    const float* bf = (const float*)d_in[4];
    float* out = (float*)d_out;

    const int nv4 = NHALF / 4 / 256;         // 2432 blocks

    k_mask   <<<dim3(32, 2, B_DIM), 128>>>(x, Wm, bm);
    k_pool   <<<dim3(2, S_CHUNKS, B_DIM), 256>>>(x);
    k_cf     <<<dim3(K_DIM, B_DIM), 512>>>();
    k_filters<<<dim3(K_DIM, 8, B_DIM), 128>>>(Wf, bf);
    k_pred   <<<dim3(32, 2, B_DIM), 128>>>(x);
    k_comb   <<<nv4, 256>>>(out);
}